// round 9
// baseline (speedup 1.0000x reference)
#include <cuda_runtime.h>

// GraphConvolution_LEGNN: out = 0.9 * rownorm1(A ⊙ same_class_mask) @ x + 0.1 * h0
// y one-hot -> mask[i][j] = (label[i]==label[j]); A ∈ {0,1}.
// R2: per-class column lists -> gather only ~N/C=625 A entries per row.
// R7 lesson: gather is DRAM-BYTE bound. Measured 374MB == 128B-line-granularity
//   model (350MB A + 30MB misc); 32B-sector model predicts 191MB. All gathers
//   used __ldcs.
// R8 EXPERIMENT (single variable): A gather via plain __ldg (default policy)
//   instead of __ldcs. If .cs was promoting DRAM fills to full 128B lines,
//   traffic drops to ~200MB and main kernel ~40us.
//
// Inputs: d_in[0]=x [N,F] f32, d_in[1]=A [N,N] f32, d_in[2]=h0 [N,F] f32,
//         d_in[3]=y [N,C] f32.  Output: f32 [N,F].

#define N_NODES 10000
#define F_DIM   256
#define C_CLS   16
#define CAP     1024   // per-row neighbor capacity (expected ~6, worst ~40)

__device__ int g_labels[N_NODES];
__device__ int g_ccnt[C_CLS];          // zero at module load; self-reset each launch
__device__ int g_done;                 // ticket; zero at load; self-reset
__device__ int g_cols[C_CLS * N_NODES];

// Wide parallel prep: label from one-hot row (exact iota dot), write labels,
// atomic scatter into class list (order irrelevant).
__global__ __launch_bounds__(256)
void prep_kernel(const float* __restrict__ y) {
    int i = blockIdx.x * blockDim.x + threadIdx.x;
    if (i >= N_NODES) return;
    const float* yr = y + (size_t)i * C_CLS;
    float s = 0.0f;
#pragma unroll
    for (int k = 0; k < C_CLS; ++k) s = fmaf((float)k, yr[k], s);
    int lab = __float2int_rn(s);
    g_labels[i] = lab;
    int p = atomicAdd(&g_ccnt[lab], 1);
    g_cols[lab * N_NODES + p] = i;
}

__global__ __launch_bounds__(F_DIM)
void gcn_row_kernel(const float* __restrict__ x,
                    const float* __restrict__ A,
                    const float* __restrict__ h0,
                    float* __restrict__ out) {
    __shared__ int   s_idx[CAP];
    __shared__ float s_val[CAP];
    __shared__ int   s_cnt;

    const int row = blockIdx.x;
    const int tid = threadIdx.x;

    if (tid == 0) s_cnt = 0;
    __syncthreads();

    const int myc  = g_labels[row];
    const int ccnt = g_ccnt[myc];
    const int* __restrict__ clist = g_cols + myc * N_NODES;
    const float* __restrict__ Arow = A + (size_t)row * N_NODES;

    // Gather same-class columns. PLAIN loads (no .cs): sectored L2 should fill
    // only the missing 32B sector from DRAM instead of a full 128B line.
    {
        const int k0 = tid, k1 = tid + F_DIM, k2 = tid + 2 * F_DIM;
        const bool p0 = k0 < ccnt, p1 = k1 < ccnt, p2 = k2 < ccnt;
        int c0 = 0, c1 = 0, c2 = 0;
        if (p0) c0 = __ldg(&clist[k0]);
        if (p1) c1 = __ldg(&clist[k1]);
        if (p2) c2 = __ldg(&clist[k2]);
        float a0 = 0.0f, a1 = 0.0f, a2 = 0.0f;
        if (p0) a0 = __ldg(&Arow[c0]);
        if (p1) a1 = __ldg(&Arow[c1]);
        if (p2) a2 = __ldg(&Arow[c2]);
        if (a0 != 0.0f) { int p = atomicAdd(&s_cnt, 1); if (p < CAP) { s_idx[p] = c0; s_val[p] = a0; } }
        if (a1 != 0.0f) { int p = atomicAdd(&s_cnt, 1); if (p < CAP) { s_idx[p] = c1; s_val[p] = a1; } }
        if (a2 != 0.0f) { int p = atomicAdd(&s_cnt, 1); if (p < CAP) { s_idx[p] = c2; s_val[p] = a2; } }
        // Generality tail (not taken for this distribution: ccnt ~ 625 +/- 24).
        for (int k = 3 * F_DIM + tid; k < ccnt; k += F_DIM) {
            int col  = __ldg(&clist[k]);
            float av = __ldg(&Arow[col]);
            if (av != 0.0f) { int p = atomicAdd(&s_cnt, 1); if (p < CAP) { s_idx[p] = col; s_val[p] = av; } }
        }
    }
    __syncthreads();

    const int cnt = min(s_cnt, CAP);

    // Drain: thread tid owns feature column tid; x rows are mostly L2 hits.
    float acc = 0.0f, sumw = 0.0f;
    int k = 0;
    for (; k + 4 <= cnt; k += 4) {
        int   c0 = s_idx[k],     c1 = s_idx[k + 1];
        int   c2 = s_idx[k + 2], c3 = s_idx[k + 3];
        float w0 = s_val[k],     w1 = s_val[k + 1];
        float w2 = s_val[k + 2], w3 = s_val[k + 3];
        float v0 = __ldg(&x[(size_t)c0 * F_DIM + tid]);
        float v1 = __ldg(&x[(size_t)c1 * F_DIM + tid]);
        float v2 = __ldg(&x[(size_t)c2 * F_DIM + tid]);
        float v3 = __ldg(&x[(size_t)c3 * F_DIM + tid]);
        acc  += w0 * v0 + w1 * v1 + w2 * v2 + w3 * v3;
        sumw += w0 + w1 + w2 + w3;
    }
    for (; k < cnt; ++k) {
        float w = s_val[k];
        acc  += w * __ldg(&x[(size_t)s_idx[k] * F_DIM + tid]);
        sumw += w;
    }

    float rs = fmaxf(sumw, 1e-12f);
    size_t o = (size_t)row * F_DIM + tid;
    out[o] = 0.9f * (acc / rs) + 0.1f * __ldcs(&h0[o]);

    // Self-reset for next graph replay: last block zeroes the counters.
    __syncthreads();
    if (tid == 0) {
        __threadfence();
        int t = atomicAdd(&g_done, 1);
        if (t == gridDim.x - 1) {
#pragma unroll
            for (int c = 0; c < C_CLS; ++c) g_ccnt[c] = 0;
            g_done = 0;
        }
    }
}

extern "C" void kernel_launch(void* const* d_in, const int* in_sizes, int n_in,
                              void* d_out, int out_size) {
    const float* x  = (const float*)d_in[0];
    const float* A  = (const float*)d_in[1];
    const float* h0 = (const float*)d_in[2];
    const float* y  = (const float*)d_in[3];
    float* out = (float*)d_out;

    prep_kernel<<<(N_NODES + 255) / 256, 256>>>(y);
    gcn_row_kernel<<<N_NODES, F_DIM>>>(x, A, h0, out);
}

// round 10
// speedup vs baseline: 1.0262x; 1.0262x over previous
#include <cuda_runtime.h>

// GraphConvolution_LEGNN: out = 0.9 * rownorm1(A ⊙ same_class_mask) @ x + 0.1 * h0
// y one-hot -> mask[i][j] = (label[i]==label[j]); A ∈ {0,1}.
// R2: per-class column lists -> gather only ~N/C=625 A entries per row.
// R8 lesson (falsified .cs theory): scattered gathers fill DRAM at ~128B line
//   granularity under ANY cache policy; traffic floor ~380MB. __ldcs slightly
//   better than __ldg (evict-first protects L2). Lever left = achieved BW.
// R9: 2 rows per CTA -> 6 independent A-loads in flight per thread during the
//   gather (2x MLP), same total bytes. grid 5000 x 256.
//
// Inputs: d_in[0]=x [N,F] f32, d_in[1]=A [N,N] f32, d_in[2]=h0 [N,F] f32,
//         d_in[3]=y [N,C] f32.  Output: f32 [N,F].

#define N_NODES 10000
#define F_DIM   256
#define C_CLS   16
#define CAPR    256    // per-row neighbor capacity (expected ~6, worst ~40)
#define RPC     2      // rows per CTA
#define SLOTS   3      // list slots per thread per row (3*256=768 >= max ccnt)

__device__ int g_labels[N_NODES];
__device__ int g_ccnt[C_CLS];          // zero at module load; self-reset each launch
__device__ int g_done;                 // ticket; zero at load; self-reset
__device__ int g_cols[C_CLS * N_NODES];

// Wide parallel prep: label from one-hot row (exact iota dot), write labels,
// atomic scatter into class list (order irrelevant).
__global__ __launch_bounds__(256)
void prep_kernel(const float* __restrict__ y) {
    int i = blockIdx.x * blockDim.x + threadIdx.x;
    if (i >= N_NODES) return;
    const float* yr = y + (size_t)i * C_CLS;
    float s = 0.0f;
#pragma unroll
    for (int k = 0; k < C_CLS; ++k) s = fmaf((float)k, yr[k], s);
    int lab = __float2int_rn(s);
    g_labels[i] = lab;
    int p = atomicAdd(&g_ccnt[lab], 1);
    g_cols[lab * N_NODES + p] = i;
}

__global__ __launch_bounds__(F_DIM)
void gcn_row_kernel(const float* __restrict__ x,
                    const float* __restrict__ A,
                    const float* __restrict__ h0,
                    float* __restrict__ out) {
    __shared__ int   s_idx[RPC][CAPR];
    __shared__ float s_val[RPC][CAPR];
    __shared__ int   s_cnt[RPC];

    const int tid  = threadIdx.x;
    const int row0 = blockIdx.x * RPC;

    if (tid < RPC) s_cnt[tid] = 0;
    __syncthreads();

    int         rccnt[RPC];
    const int*  rlist[RPC];
    const float* Arow[RPC];
#pragma unroll
    for (int r = 0; r < RPC; ++r) {
        int myc  = g_labels[row0 + r];
        rccnt[r] = g_ccnt[myc];
        rlist[r] = g_cols + myc * N_NODES;
        Arow[r]  = A + (size_t)(row0 + r) * N_NODES;
    }

    // High-MLP gather: 2 rows x 3 slots = 6 independent A loads in flight per
    // thread. List loads first (L2-resident), then all A loads back-to-back.
    {
        int   col[RPC][SLOTS];
        float av [RPC][SLOTS];
        bool  pr [RPC][SLOTS];
#pragma unroll
        for (int r = 0; r < RPC; ++r)
#pragma unroll
            for (int j = 0; j < SLOTS; ++j) {
                int k = tid + j * F_DIM;
                pr[r][j]  = (k < rccnt[r]);
                col[r][j] = pr[r][j] ? __ldg(&rlist[r][k]) : 0;
            }
#pragma unroll
        for (int r = 0; r < RPC; ++r)
#pragma unroll
            for (int j = 0; j < SLOTS; ++j)
                av[r][j] = pr[r][j] ? __ldcs(&Arow[r][col[r][j]]) : 0.0f;
#pragma unroll
        for (int r = 0; r < RPC; ++r)
#pragma unroll
            for (int j = 0; j < SLOTS; ++j)
                if (av[r][j] != 0.0f) {
                    int p = atomicAdd(&s_cnt[r], 1);
                    if (p < CAPR) { s_idx[r][p] = col[r][j]; s_val[r][p] = av[r][j]; }
                }
    }
    __syncthreads();

    // Drain both rows: thread tid owns feature column tid; x rows are L2 hits.
#pragma unroll
    for (int r = 0; r < RPC; ++r) {
        const int cnt = min(s_cnt[r], CAPR);
        float acc = 0.0f, sumw = 0.0f;
        int k = 0;
        for (; k + 4 <= cnt; k += 4) {
            int   c0 = s_idx[r][k],     c1 = s_idx[r][k + 1];
            int   c2 = s_idx[r][k + 2], c3 = s_idx[r][k + 3];
            float w0 = s_val[r][k],     w1 = s_val[r][k + 1];
            float w2 = s_val[r][k + 2], w3 = s_val[r][k + 3];
            float v0 = __ldg(&x[(size_t)c0 * F_DIM + tid]);
            float v1 = __ldg(&x[(size_t)c1 * F_DIM + tid]);
            float v2 = __ldg(&x[(size_t)c2 * F_DIM + tid]);
            float v3 = __ldg(&x[(size_t)c3 * F_DIM + tid]);
            acc  += w0 * v0 + w1 * v1 + w2 * v2 + w3 * v3;
            sumw += w0 + w1 + w2 + w3;
        }
        for (; k < cnt; ++k) {
            float w = s_val[r][k];
            acc  += w * __ldg(&x[(size_t)s_idx[r][k] * F_DIM + tid]);
            sumw += w;
        }
        float rs = fmaxf(sumw, 1e-12f);
        size_t o = (size_t)(row0 + r) * F_DIM + tid;
        out[o] = 0.9f * (acc / rs) + 0.1f * __ldcs(&h0[o]);
    }

    // Self-reset for next graph replay: last block zeroes the counters. This
    // block's g_ccnt reads precede the ticket (sync + program order).
    __syncthreads();
    if (tid == 0) {
        __threadfence();
        int t = atomicAdd(&g_done, 1);
        if (t == gridDim.x - 1) {
#pragma unroll
            for (int c = 0; c < C_CLS; ++c) g_ccnt[c] = 0;
            g_done = 0;
        }
    }
}

extern "C" void kernel_launch(void* const* d_in, const int* in_sizes, int n_in,
                              void* d_out, int out_size) {
    const float* x  = (const float*)d_in[0];
    const float* A  = (const float*)d_in[1];
    const float* h0 = (const float*)d_in[2];
    const float* y  = (const float*)d_in[3];
    float* out = (float*)d_out;

    prep_kernel<<<(N_NODES + 255) / 256, 256>>>(y);
    gcn_row_kernel<<<N_NODES / RPC, F_DIM>>>(x, A, h0, out);
}

// round 11
// speedup vs baseline: 1.0620x; 1.0349x over previous
#include <cuda_runtime.h>

// GraphConvolution_LEGNN: out = 0.9 * rownorm1(A ⊙ same_class_mask) @ x + 0.1 * h0
// y one-hot -> mask[i][j] = (label[i]==label[j]); A ∈ {0,1}.
// R2: per-class column lists -> gather only ~N/C=625 A entries per row.
// R8: cache-policy (.cs vs default) ~neutral on DRAM bytes; scatter traffic
//     floor ~350MB regardless.
// R9 lesson: 2 rows/CTA regressed (occupancy down, chip-level concurrency down).
//     Keep grid=10000, 1 row/CTA (R7 structure = best at 64.2us main).
// R10 lever: A-gather via ld.global.nc.L1::no_allocate — single-use data should
//     not allocate L1 lines; shrinks L1tex wavefront-queue pressure (the
//     suspected scatter-BW throttle). Plus streaming store for out.
//
// Inputs: d_in[0]=x [N,F] f32, d_in[1]=A [N,N] f32, d_in[2]=h0 [N,F] f32,
//         d_in[3]=y [N,C] f32.  Output: f32 [N,F].

#define N_NODES 10000
#define F_DIM   256
#define C_CLS   16
#define CAP     1024   // per-row neighbor capacity (expected ~6, worst ~40)

__device__ int g_labels[N_NODES];
__device__ int g_ccnt[C_CLS];          // zero at module load; self-reset each launch
__device__ int g_done;                 // ticket; zero at load; self-reset
__device__ int g_cols[C_CLS * N_NODES];

// Single-use global load: no L1 allocation, read-only path.
__device__ __forceinline__ float ldg_noL1(const float* p) {
    float v;
    asm volatile("ld.global.nc.L1::no_allocate.f32 %0, [%1];"
                 : "=f"(v) : "l"(p));
    return v;
}

// Wide parallel prep: label from one-hot row (exact iota dot), write labels,
// atomic scatter into class list (order irrelevant).
__global__ __launch_bounds__(256)
void prep_kernel(const float* __restrict__ y) {
    int i = blockIdx.x * blockDim.x + threadIdx.x;
    if (i >= N_NODES) return;
    const float* yr = y + (size_t)i * C_CLS;
    float s = 0.0f;
#pragma unroll
    for (int k = 0; k < C_CLS; ++k) s = fmaf((float)k, yr[k], s);
    int lab = __float2int_rn(s);
    g_labels[i] = lab;
    int p = atomicAdd(&g_ccnt[lab], 1);
    g_cols[lab * N_NODES + p] = i;
}

__global__ __launch_bounds__(F_DIM)
void gcn_row_kernel(const float* __restrict__ x,
                    const float* __restrict__ A,
                    const float* __restrict__ h0,
                    float* __restrict__ out) {
    __shared__ int   s_idx[CAP];
    __shared__ float s_val[CAP];
    __shared__ int   s_cnt;

    const int row = blockIdx.x;
    const int tid = threadIdx.x;

    if (tid == 0) s_cnt = 0;
    __syncthreads();

    const int myc  = g_labels[row];
    const int ccnt = g_ccnt[myc];
    const int* __restrict__ clist = g_cols + myc * N_NODES;
    const float* __restrict__ Arow = A + (size_t)row * N_NODES;

    // Gather same-class columns; A loads bypass L1 allocation (single-use).
    {
        const int k0 = tid, k1 = tid + F_DIM, k2 = tid + 2 * F_DIM;
        const bool p0 = k0 < ccnt, p1 = k1 < ccnt, p2 = k2 < ccnt;
        int c0 = 0, c1 = 0, c2 = 0;
        if (p0) c0 = __ldg(&clist[k0]);
        if (p1) c1 = __ldg(&clist[k1]);
        if (p2) c2 = __ldg(&clist[k2]);
        float a0 = 0.0f, a1 = 0.0f, a2 = 0.0f;
        if (p0) a0 = ldg_noL1(&Arow[c0]);
        if (p1) a1 = ldg_noL1(&Arow[c1]);
        if (p2) a2 = ldg_noL1(&Arow[c2]);
        if (a0 != 0.0f) { int p = atomicAdd(&s_cnt, 1); if (p < CAP) { s_idx[p] = c0; s_val[p] = a0; } }
        if (a1 != 0.0f) { int p = atomicAdd(&s_cnt, 1); if (p < CAP) { s_idx[p] = c1; s_val[p] = a1; } }
        if (a2 != 0.0f) { int p = atomicAdd(&s_cnt, 1); if (p < CAP) { s_idx[p] = c2; s_val[p] = a2; } }
        // Generality tail (not taken for this distribution: ccnt ~ 625 +/- 24).
        for (int k = 3 * F_DIM + tid; k < ccnt; k += F_DIM) {
            int col  = __ldg(&clist[k]);
            float av = ldg_noL1(&Arow[col]);
            if (av != 0.0f) { int p = atomicAdd(&s_cnt, 1); if (p < CAP) { s_idx[p] = col; s_val[p] = av; } }
        }
    }
    __syncthreads();

    const int cnt = min(s_cnt, CAP);

    // Drain: thread tid owns feature column tid; x rows are L2 hits.
    float acc = 0.0f, sumw = 0.0f;
    int k = 0;
    for (; k + 4 <= cnt; k += 4) {
        int   c0 = s_idx[k],     c1 = s_idx[k + 1];
        int   c2 = s_idx[k + 2], c3 = s_idx[k + 3];
        float w0 = s_val[k],     w1 = s_val[k + 1];
        float w2 = s_val[k + 2], w3 = s_val[k + 3];
        float v0 = __ldg(&x[(size_t)c0 * F_DIM + tid]);
        float v1 = __ldg(&x[(size_t)c1 * F_DIM + tid]);
        float v2 = __ldg(&x[(size_t)c2 * F_DIM + tid]);
        float v3 = __ldg(&x[(size_t)c3 * F_DIM + tid]);
        acc  += w0 * v0 + w1 * v1 + w2 * v2 + w3 * v3;
        sumw += w0 + w1 + w2 + w3;
    }
    for (; k < cnt; ++k) {
        float w = s_val[k];
        acc  += w * __ldg(&x[(size_t)s_idx[k] * F_DIM + tid]);
        sumw += w;
    }

    float rs = fmaxf(sumw, 1e-12f);
    size_t o = (size_t)row * F_DIM + tid;
    float res = 0.9f * (acc / rs) + 0.1f * __ldcs(&h0[o]);
    __stcs(&out[o], res);   // write-once stream

    // Self-reset for next graph replay: last block zeroes the counters. This
    // block's g_ccnt reads precede the ticket (sync + program order).
    __syncthreads();
    if (tid == 0) {
        __threadfence();
        int t = atomicAdd(&g_done, 1);
        if (t == gridDim.x - 1) {
#pragma unroll
            for (int c = 0; c < C_CLS; ++c) g_ccnt[c] = 0;
            g_done = 0;
        }
    }
}

extern "C" void kernel_launch(void* const* d_in, const int* in_sizes, int n_in,
                              void* d_out, int out_size) {
    const float* x  = (const float*)d_in[0];
    const float* A  = (const float*)d_in[1];
    const float* h0 = (const float*)d_in[2];
    const float* y  = (const float*)d_in[3];
    float* out = (float*)d_out;

    prep_kernel<<<(N_NODES + 255) / 256, 256>>>(y);
    gcn_row_kernel<<<N_NODES, F_DIM>>>(x, A, h0, out);
}